// round 9
// baseline (speedup 1.0000x reference)
#include <cuda_runtime.h>
#include <cuda_bf16.h>
#include <cstdint>

#define MAX_GRID_P 2048
__device__ float g_partials[MAX_GRID_P];
__device__ int   g_done_ctr = 0;

// ---------------------------------------------------------------------------
// PTX helpers
// ---------------------------------------------------------------------------
__device__ __forceinline__ uint32_t smem_u32(const void* p) {
    uint32_t a;
    asm("{ .reg .u64 t; cvta.to.shared.u64 t, %1; cvt.u32.u64 %0, t; }"
        : "=r"(a) : "l"(p));
    return a;
}
__device__ __forceinline__ void mbar_init(uint32_t mbar, uint32_t cnt) {
    asm volatile("mbarrier.init.shared.b64 [%0], %1;" :: "r"(mbar), "r"(cnt) : "memory");
}
__device__ __forceinline__ void mbar_arrive(uint32_t mbar) {
    asm volatile("mbarrier.arrive.shared.b64 _, [%0];" :: "r"(mbar) : "memory");
}
__device__ __forceinline__ void mbar_expect_tx(uint32_t mbar, uint32_t bytes) {
    asm volatile("mbarrier.arrive.expect_tx.shared.b64 _, [%0], %1;"
                 :: "r"(mbar), "r"(bytes) : "memory");
}
__device__ __forceinline__ void mbar_wait(uint32_t mbar, uint32_t parity) {
    uint32_t done;
    do {
        asm volatile(
            "{\n\t.reg .pred p;\n\t"
            "mbarrier.try_wait.parity.acquire.cta.shared::cta.b64 p, [%1], %2, 0x989680;\n\t"
            "selp.b32 %0, 1, 0, p;\n\t}"
            : "=r"(done) : "r"(mbar), "r"(parity) : "memory");
    } while (!done);
}
// 1D bulk copy GMEM -> SMEM with mbarrier complete_tx.
__device__ __forceinline__ void bulk_g2s(uint32_t dst, const void* src,
                                         uint32_t bytes, uint32_t mbar) {
    asm volatile(
        "cp.async.bulk.shared::cluster.global.mbarrier::complete_tx::bytes "
        "[%0], [%1], %2, [%3];"
        :: "r"(dst), "l"(src), "r"(bytes), "r"(mbar) : "memory");
}

// ---------------------------------------------------------------------------
// Persistent TMA-pipeline kernel.
//   grid = 296 CTAs (2/SM); CTA b owns rows [b*B/G, (b+1)*B/G).
//   Warp 7 (producer) streams valid half-row prefixes into an NST-stage smem
//   ring via cp.async.bulk (bytes-in-flight decoupled from registers).
//   Warps 0..6 (consumers) process tiles from smem. Tile k -> warp k%7
//   (static), fixed accumulation order -> deterministic.
//   loss = (1/B) * sum_row (1/L) * sum_{t<L} (pred - log(align))^2
// ---------------------------------------------------------------------------
template <int BLOCK>
__global__ void __launch_bounds__(BLOCK)
dploss_pipe_kernel(const float* __restrict__ pred,
                   const float* __restrict__ align,
                   const int* __restrict__ lens,
                   float* __restrict__ out,
                   int C,          // float4 chunks per row
                   int H0,         // chunks in first half = (C+1)/2
                   int NST,        // ring stages
                   int stageTotal, // bytes per stage (2 * H0 * 16)
                   int B) {
    extern __shared__ char smem[];
    const int tid  = threadIdx.x;
    const int wid  = tid >> 5;
    const int lane = tid & 31;
    const int G    = gridDim.x;

    const uint32_t smemBase = smem_u32(smem);
    const uint32_t mbarBase = smemBase + (uint32_t)NST * (uint32_t)stageTotal;
    // full[s] at mbarBase + 16s, empty[s] at +16s+8

    if (tid == 0) {
        for (int s = 0; s < NST; s++) {
            mbar_init(mbarBase + 16 * s,     1);   // full: producer expect_tx
            mbar_init(mbarBase + 16 * s + 8, 1);   // empty: consuming warp
        }
        asm volatile("fence.proxy.async.shared::cta;" ::: "memory");
    }
    __syncthreads();

    // This CTA's row range (balanced partition).
    const int r0 = (int)((long long)blockIdx.x * B / G);
    const int r1 = (int)((long long)(blockIdx.x + 1) * B / G);

    if (wid == 7) {
        // ---------------- producer ----------------
        if (lane == 0) {
            int k = 0;
            for (int r = r0; r < r1; r++) {
                const int L = __ldg(lens + r);
                const int V = (L + 3) >> 2;            // valid chunks in row
                #pragma unroll 1
                for (int h = 0; h < 2; h++) {
                    int vh = min(V - h * H0, (h ? C - H0 : H0));
                    if (vh <= 0) continue;
                    const int slot = k % NST;
                    const uint32_t phase = (uint32_t)((k / NST) & 1);
                    mbar_wait(mbarBase + 16 * slot + 8, phase ^ 1);  // empty
                    const uint32_t nb = (uint32_t)vh * 16u;
                    const uint32_t full = mbarBase + 16 * slot;
                    mbar_expect_tx(full, 2u * nb);
                    const size_t off = ((size_t)r * (size_t)C + (size_t)h * H0) * 16u;
                    const uint32_t dst = smemBase + (uint32_t)slot * stageTotal;
                    bulk_g2s(dst,                    (const char*)pred  + off, nb, full);
                    bulk_g2s(dst + (uint32_t)H0*16u, (const char*)align + off, nb, full);
                    k++;
                }
            }
        }
    } else {
        // ---------------- consumers (warps 0..6) ----------------
        float acc = 0.0f;
        int k = 0;
        for (int r = r0; r < r1; r++) {
            const int L = __ldg(lens + r);
            const int V = (L + 3) >> 2;
            const float rcpL = __frcp_rn((float)L);
            #pragma unroll 1
            for (int h = 0; h < 2; h++) {
                int vh = min(V - h * H0, (h ? C - H0 : H0));
                if (vh <= 0) continue;
                if (k % 7 == wid) {
                    const int slot = k % NST;
                    const uint32_t phase = (uint32_t)((k / NST) & 1);
                    mbar_wait(mbarBase + 16 * slot, phase);          // full
                    const char* sp = smem + (size_t)slot * stageTotal;
                    const char* sa = sp + (size_t)H0 * 16u;
                    float st = 0.0f;
                    const int hbase = h * H0;
                    for (int c = lane; c < vh; c += 32) {
                        float4 p = *reinterpret_cast<const float4*>(sp + (size_t)c * 16u);
                        float4 a = *reinterpret_cast<const float4*>(sa + (size_t)c * 16u);
                        const int rem = L - ((hbase + c) << 2);
                        float d = p.x - __logf(a.x);
                        st = fmaf(d, d, st);
                        if (rem > 1) { d = p.y - __logf(a.y); st = fmaf(d, d, st); }
                        if (rem > 2) { d = p.z - __logf(a.z); st = fmaf(d, d, st); }
                        if (rem > 3) { d = p.w - __logf(a.w); st = fmaf(d, d, st); }
                    }
                    acc = fmaf(st, rcpL, acc);
                    __syncwarp();
                    if (lane == 0)
                        mbar_arrive(mbarBase + 16 * slot + 8);       // empty
                }
                k++;
            }
        }

        // Warp reduction (fixed order).
        #pragma unroll
        for (int off = 16; off > 0; off >>= 1)
            acc += __shfl_down_sync(0xFFFFFFFFu, acc, off);
        __shared__ float s_wacc[8];
        if (lane == 0) s_wacc[wid] = acc;
        __syncthreads();   // producer reaches the matching sync below

        if (tid == 0) {
            float v = 0.0f;
            #pragma unroll
            for (int w = 0; w < 7; w++) v += s_wacc[w];
            g_partials[blockIdx.x] = v;
        }
    }

    // Producer joins the consumer __syncthreads here.
    if (wid == 7) __syncthreads();
    __syncthreads();

    __shared__ bool s_is_last;
    if (tid == 0) {
        __threadfence();
        int old = atomicAdd(&g_done_ctr, 1);
        s_is_last = (old == G - 1);
    }
    __syncthreads();

    if (s_is_last) {
        float v = 0.0f;
        for (int i = tid; i < G; i += BLOCK)      // fixed order
            v += g_partials[i];
        __shared__ float s_fin[BLOCK / 32];
        #pragma unroll
        for (int off = 16; off > 0; off >>= 1)
            v += __shfl_down_sync(0xFFFFFFFFu, v, off);
        if ((tid & 31) == 0) s_fin[tid >> 5] = v;
        __syncthreads();
        if (tid == 0) {
            float t = 0.0f;
            #pragma unroll
            for (int w = 0; w < BLOCK / 32; w++) t += s_fin[w];
            out[0] = t / (float)B;
            g_done_ctr = 0;                        // reset for replay
        }
    }
}

extern "C" void kernel_launch(void* const* d_in, const int* in_sizes, int n_in,
                              void* d_out, int out_size) {
    const float* pred  = (const float*)d_in[0];
    const float* align = (const float*)d_in[1];
    const int*   lens  = (const int*)d_in[2];
    float* out = (float*)d_out;

    const int B = in_sizes[2];
    const int T = in_sizes[0] / B;
    const int C = T >> 2;                // float4 chunks per row
    const int H0 = (C + 1) >> 1;         // first-half chunks
    const int stageTotal = 2 * H0 * 16;  // pred half + align half

    int NST = 8;
    while (NST > 2 && NST * stageTotal > 160 * 1024) NST >>= 1;

    constexpr int BLOCK = 256;
    int grid = 296;                      // 2 CTAs / SM
    if (grid > B) grid = B;
    if (grid > MAX_GRID_P) grid = MAX_GRID_P;

    const int smemBytes = NST * stageTotal + NST * 16 + 64;
    static int configured = -1;
    if (configured != smemBytes) {
        cudaFuncSetAttribute(dploss_pipe_kernel<BLOCK>,
                             cudaFuncAttributeMaxDynamicSharedMemorySize,
                             smemBytes);
        configured = smemBytes;
    }

    dploss_pipe_kernel<BLOCK><<<grid, BLOCK, smemBytes>>>(
        pred, align, lens, out, C, H0, NST, stageTotal, B);
}